// round 6
// baseline (speedup 1.0000x reference)
#include <cuda_runtime.h>
#include <math.h>

#define BB 8
#define SS 4096
#define DD 1024
#define NN 64
#define SHIFT 2048
#define NCH 128
#define CHL 32
#define TILE_A 128
#define TILE_C 32

// ---------------- scratch (device globals) ----------------
__device__ float g_wT[DD * 128];            // [d][o]: o=2n -> lnw*kw, o=2n+1 -> lnw*vw
__device__ float g_wsum[128];
__device__ float g_lbsum[128];
__device__ float g_gate[DD];
__device__ float g_w[NN];                   // exp(time_decay)
__device__ float g_exptf[NN];               // exp(time_first)
__device__ float4 g_owQ[16 * DD];           // [n4][d] = ow[d][4n4..4n4+3]
__device__ float g_wkv[BB * SS * NN];
__device__ float g_chunk[BB * NCH * NN];
__device__ float g_carry[BB * NCH * NN];

// ---------------- packed fp32x2 FMA (sm_103a FFMA2) ----------------
__device__ __forceinline__ float2 ffma2(float2 a, float2 b, float2 c) {
    float2 d;
    asm("fma.rn.f32x2 %0, %1, %2, %3;"
        : "=l"(*reinterpret_cast<unsigned long long*>(&d))
        : "l"(*reinterpret_cast<unsigned long long*>(&a)),
          "l"(*reinterpret_cast<unsigned long long*>(&b)),
          "l"(*reinterpret_cast<unsigned long long*>(&c)));
    return d;
}

// ---------------- prep kernels ----------------
__global__ void prep_a(const float* __restrict__ kw, const float* __restrict__ vw,
                       const float* __restrict__ lnw, const float* __restrict__ tsg,
                       const float* __restrict__ td, const float* __restrict__ tf) {
    int idx = blockIdx.x * 256 + threadIdx.x;   // 0..131071
    int d = idx >> 7;
    int o = idx & 127;
    int n = o >> 1;
    const float* src = (o & 1) ? vw : kw;
    g_wT[idx] = lnw[d] * src[n * DD + d];
    if (o == 0) g_gate[d] = 1.f / (1.f + expf(-tsg[d]));
    if (idx < NN) g_w[idx] = expf(td[idx]);
    else if (idx < 2 * NN) g_exptf[idx - NN] = expf(tf[idx - NN]);
}

__global__ void prep_ow(const float* __restrict__ ow) {
    int idx = blockIdx.x * 256 + threadIdx.x;   // 0..16383
    int d = idx & (DD - 1);
    int n4 = idx >> 10;
    g_owQ[idx] = *reinterpret_cast<const float4*>(&ow[d * NN + 4 * n4]);
}

__global__ void prep_b(const float* __restrict__ kw, const float* __restrict__ vw,
                       const float* __restrict__ lnb) {
    __shared__ float red[2][8];
    int o = blockIdx.x;
    int n = o >> 1;
    const float* src = (o & 1) ? vw : kw;
    int tid = threadIdx.x;
    float ws = 0.f, lb = 0.f;
    for (int d = tid; d < DD; d += 256) {
        ws += g_wT[d * 128 + o];
        lb += lnb[d] * src[n * DD + d];
    }
#pragma unroll
    for (int off = 16; off; off >>= 1) {
        ws += __shfl_xor_sync(0xffffffffu, ws, off);
        lb += __shfl_xor_sync(0xffffffffu, lb, off);
    }
    if ((tid & 31) == 0) { red[0][tid >> 5] = ws; red[1][tid >> 5] = lb; }
    __syncthreads();
    if (tid == 0) {
        float a = 0.f, c = 0.f;
#pragma unroll
        for (int i = 0; i < 8; i++) { a += red[0][i]; c += red[1][i]; }
        g_wsum[o] = a;
        g_lbsum[o] = c;
    }
}

// ---------------- kernel A: pipelined blend+LN+KV proj+wkv+chunk sums ----------------
// grid 256, 512 threads. 16 chunks of 64 d, double-buffered xs+wsm.
// smem floats: gate[1024] | xs0[8192] xs1[8192] | wsm0[8192] wsm1[8192] | mu[128] inv[128]
__global__ void __launch_bounds__(512, 1)
kernelA(const float* __restrict__ x) {
    extern __shared__ float sm[];
    float* gate_s = sm;
    float* xsb[2] = { sm + 1024, sm + 1024 + 8192 };
    float* wsb[2] = { sm + 17408, sm + 17408 + 8192 };
    float* mu_s  = sm + 33792;
    float* inv_s = sm + 33920;

    int b = blockIdx.x >> 5;
    int cb = blockIdx.x & 31;
    int t0 = cb * TILE_A;
    int tid = threadIdx.x;
    int lane = tid & 31;
    int warp = tid >> 5;
    int g16 = tid >> 4;              // row group 0..31
    int c4o = (tid & 15) * 4;        // d-offset within chunk (x staging)
    int o4  = (tid & 31) * 4;        // weight col offset
    int dl0 = tid >> 5;              // weight row base (q stride 16)

    // x row-base pointers (q-th row = +q*32*DD)
    int trow = t0 + g16;
    const float* xt0 = x + ((size_t)(b * SS) + trow) * DD + c4o;
    const float* xc0 = x + ((size_t)(b * SS) + (trow ^ SHIFT)) * DD + c4o;
    const float* wp0 = g_wT + dl0 * 128 + o4;

    // stage gate
    if (tid < 256)
        reinterpret_cast<float4*>(gate_s)[tid] =
            reinterpret_cast<const float4*>(g_gate)[tid];

    float st_sum[4], st_sq[4];
#pragma unroll
    for (int q = 0; q < 4; q++) { st_sum[q] = 0.f; st_sq[q] = 0.f; }

    float2 acc[8][2];
#pragma unroll
    for (int i = 0; i < 8; i++) { acc[i][0] = make_float2(0.f, 0.f); acc[i][1] = make_float2(0.f, 0.f); }

    float4 pxt[4], pxc[4], pw[4];
    // prologue: LDG chunk 0
#pragma unroll
    for (int q = 0; q < 4; q++) {
        pxt[q] = *reinterpret_cast<const float4*>(xt0 + (size_t)q * 32 * DD);
        pxc[q] = *reinterpret_cast<const float4*>(xc0 + (size_t)q * 32 * DD);
        pw[q]  = *reinterpret_cast<const float4*>(wp0 + q * 2048);
    }
    __syncthreads();   // gate visible
    // blend chunk 0 -> buffers 0
#pragma unroll
    for (int q = 0; q < 4; q++) {
        float4 g4 = *reinterpret_cast<const float4*>(&gate_s[c4o]);
        float4 s;
        s.x = pxt[q].x + g4.x * (pxc[q].x - pxt[q].x);
        s.y = pxt[q].y + g4.y * (pxc[q].y - pxt[q].y);
        s.z = pxt[q].z + g4.z * (pxc[q].z - pxt[q].z);
        s.w = pxt[q].w + g4.w * (pxc[q].w - pxt[q].w);
        st_sum[q] += s.x + s.y + s.z + s.w;
        st_sq[q]  += s.x * s.x + s.y * s.y + s.z * s.z + s.w * s.w;
        *reinterpret_cast<float4*>(&xsb[0][(q * 32 + g16) * 64 + c4o]) = s;
        *reinterpret_cast<float4*>(&wsb[0][(q * 16 + dl0) * 128 + o4]) = pw[q];
    }
    __syncthreads();

#pragma unroll 1
    for (int ch = 0; ch < 16; ch++) {
        int buf = ch & 1;
        // prefetch chunk ch+1
        if (ch < 15) {
            int off = (ch + 1) * 64;
#pragma unroll
            for (int q = 0; q < 4; q++) {
                pxt[q] = *reinterpret_cast<const float4*>(xt0 + (size_t)q * 32 * DD + off);
                pxc[q] = *reinterpret_cast<const float4*>(xc0 + (size_t)q * 32 * DD + off);
                pw[q]  = *reinterpret_cast<const float4*>(wp0 + q * 2048 + (ch + 1) * 8192);
            }
        }
        // GEMM on current buffers
        const float* aB = &xsb[buf][(warp * 8) * 64];
        const float* wB = wsb[buf];
#pragma unroll 4
        for (int dl4 = 0; dl4 < 16; dl4++) {
            float4 wv[4];
#pragma unroll
            for (int k = 0; k < 4; k++)
                wv[k] = *reinterpret_cast<const float4*>(&wB[(dl4 * 4 + k) * 128 + lane * 4]);
            float4 av[8];
#pragma unroll
            for (int i = 0; i < 8; i++)
                av[i] = *reinterpret_cast<const float4*>(&aB[i * 64 + dl4 * 4]);
#pragma unroll
            for (int i = 0; i < 8; i++) {
                float2 p;
                p = make_float2(av[i].x, av[i].x);
                acc[i][0] = ffma2(p, make_float2(wv[0].x, wv[0].y), acc[i][0]);
                acc[i][1] = ffma2(p, make_float2(wv[0].z, wv[0].w), acc[i][1]);
                p = make_float2(av[i].y, av[i].y);
                acc[i][0] = ffma2(p, make_float2(wv[1].x, wv[1].y), acc[i][0]);
                acc[i][1] = ffma2(p, make_float2(wv[1].z, wv[1].w), acc[i][1]);
                p = make_float2(av[i].z, av[i].z);
                acc[i][0] = ffma2(p, make_float2(wv[2].x, wv[2].y), acc[i][0]);
                acc[i][1] = ffma2(p, make_float2(wv[2].z, wv[2].w), acc[i][1]);
                p = make_float2(av[i].w, av[i].w);
                acc[i][0] = ffma2(p, make_float2(wv[3].x, wv[3].y), acc[i][0]);
                acc[i][1] = ffma2(p, make_float2(wv[3].z, wv[3].w), acc[i][1]);
            }
        }
        // blend + store prefetched chunk into other buffers
        if (ch < 15) {
            float4 g4 = *reinterpret_cast<const float4*>(&gate_s[(ch + 1) * 64 + c4o]);
            float* xd = xsb[buf ^ 1];
            float* wd = wsb[buf ^ 1];
#pragma unroll
            for (int q = 0; q < 4; q++) {
                float4 s;
                s.x = pxt[q].x + g4.x * (pxc[q].x - pxt[q].x);
                s.y = pxt[q].y + g4.y * (pxc[q].y - pxt[q].y);
                s.z = pxt[q].z + g4.z * (pxc[q].z - pxt[q].z);
                s.w = pxt[q].w + g4.w * (pxc[q].w - pxt[q].w);
                st_sum[q] += s.x + s.y + s.z + s.w;
                st_sq[q]  += s.x * s.x + s.y * s.y + s.z * s.z + s.w * s.w;
                *reinterpret_cast<float4*>(&xd[(q * 32 + g16) * 64 + c4o]) = s;
                *reinterpret_cast<float4*>(&wd[(q * 16 + dl0) * 128 + o4]) = pw[q];
            }
        }
        __syncthreads();
    }

    // ---- LN stats finalize (16-thread groups share a row) ----
#pragma unroll
    for (int q = 0; q < 4; q++) {
        float s = st_sum[q], qq = st_sq[q];
#pragma unroll
        for (int off = 8; off; off >>= 1) {
            s  += __shfl_xor_sync(0xffffffffu, s, off);
            qq += __shfl_xor_sync(0xffffffffu, qq, off);
        }
        if ((lane & 15) == 0) {
            int row = q * 32 + g16;
            float mu = s * (1.f / DD);
            float var = qq * (1.f / DD) - mu * mu;
            mu_s[row] = mu;
            inv_s[row] = rsqrtf(var + 1e-5f);
        }
    }
    __syncthreads();

    // ---- epilogue: LN fold + wkv ----
    float* wkv_s = wsb[0];                   // 8192 floats overlay
    int n0 = lane * 2;
    int n1 = n0 + 1;
#pragma unroll
    for (int i = 0; i < 8; i++) {
        int r = warp * 8 + i;
        int t = t0 + r;
        float mu = mu_s[r], inv = inv_s[r];
        float k0 = inv * (acc[i][0].x - mu * g_wsum[2 * n0])     + g_lbsum[2 * n0];
        float v0 = inv * (acc[i][0].y - mu * g_wsum[2 * n0 + 1]) + g_lbsum[2 * n0 + 1];
        float wk0 = expf(-g_exptf[n0] * k0) * v0;
        float k1 = inv * (acc[i][1].x - mu * g_wsum[2 * n1])     + g_lbsum[2 * n1];
        float v1 = inv * (acc[i][1].y - mu * g_wsum[2 * n1 + 1]) + g_lbsum[2 * n1 + 1];
        float wk1 = expf(-g_exptf[n1] * k1) * v1;
        float2 wv = make_float2(wk0, wk1);
        *reinterpret_cast<float2*>(&g_wkv[((size_t)(b * SS) + t) * NN + n0]) = wv;
        *reinterpret_cast<float2*>(&wkv_s[r * NN + n0]) = wv;
    }
    __syncthreads();
    if (tid < 256) {
        int sub = tid >> 6;
        int n = tid & 63;
        float w = g_w[n];
        float a = 0.f;
#pragma unroll
        for (int r = 0; r < 32; r++) a = a * w + wkv_s[(sub * 32 + r) * NN + n];
        g_chunk[((size_t)b * NCH + cb * 4 + sub) * NN + n] = a;
    }
}

// ---------------- carry prefix over chunks ----------------
__global__ void scan_carry(const float* __restrict__ td, float* __restrict__ lastout,
                           int write_last) {
    int tid = threadIdx.x;                  // 512 threads
    int n = tid & (NN - 1);
    int b = tid >> 6;
    float wL = expf((float)CHL * td[n]);
    float carry = 0.f;
    for (int c0 = 0; c0 < NCH; c0 += 8) {
        float v[8];
#pragma unroll
        for (int i = 0; i < 8; i++) v[i] = g_chunk[((size_t)b * NCH + c0 + i) * NN + n];
#pragma unroll
        for (int i = 0; i < 8; i++) {
            g_carry[((size_t)b * NCH + c0 + i) * NN + n] = carry;
            carry = carry * wL + v[i];
        }
    }
    if (write_last) lastout[b * NN + n] = carry;
}

// ---------------- kernel C: fused scan + output projection ----------------
// grid 1024, 1024 threads (32 warps). wg = tid>>9 owns rows [16wg,16wg+16);
// dtid = tid&511 owns d0=dtid, d1=dtid+512.
#define SPITCH 36
__global__ void __launch_bounds__(1024, 1)
kernelC(float* __restrict__ out) {
    __shared__ float wk[TILE_C * NN];       // 2048
    __shared__ float sT[NN * SPITCH];       // 2304

    int b = blockIdx.x >> 7;
    int c = blockIdx.x & 127;
    int t0 = c * TILE_C;
    int tid = threadIdx.x;
    int wg = tid >> 9;
    int dtid = tid & 511;

    if (tid < 512)
        reinterpret_cast<float4*>(wk)[tid] =
            reinterpret_cast<const float4*>(&g_wkv[((size_t)(b * SS) + t0) * NN])[tid];
    __syncthreads();

    if (tid < NN) {
        int n = tid;
        float w = g_w[n];
        float st = g_carry[((size_t)b * NCH + c) * NN + n];
#pragma unroll
        for (int r = 0; r < TILE_C; r++) {
            st = st * w + wk[r * NN + n];
            sT[n * SPITCH + r] = st;
        }
    }
    __syncthreads();

    // acc[p][h]: p = row pair within 16-row group, h = d half
    float2 acc[8][2];
#pragma unroll
    for (int p = 0; p < 8; p++) { acc[p][0] = make_float2(0.f, 0.f); acc[p][1] = make_float2(0.f, 0.f); }

    const float* sBase = &sT[wg * 16];
#pragma unroll 2
    for (int n4 = 0; n4 < 16; n4++) {
        float4 wA = __ldg(&g_owQ[n4 * 1024 + dtid]);
        float4 wB = __ldg(&g_owQ[n4 * 1024 + 512 + dtid]);
#pragma unroll
        for (int j = 0; j < 4; j++) {
            int n = 4 * n4 + j;
            float wa = (j == 0) ? wA.x : (j == 1) ? wA.y : (j == 2) ? wA.z : wA.w;
            float wb = (j == 0) ? wB.x : (j == 1) ? wB.y : (j == 2) ? wB.z : wB.w;
            float2 wa2 = make_float2(wa, wa);
            float2 wb2 = make_float2(wb, wb);
            const float* sb = sBase + n * SPITCH;
#pragma unroll
            for (int q = 0; q < 4; q++) {
                float4 s4 = *reinterpret_cast<const float4*>(sb + 4 * q);
                float2 slo = make_float2(s4.x, s4.y);
                float2 shi = make_float2(s4.z, s4.w);
                acc[2 * q][0]     = ffma2(slo, wa2, acc[2 * q][0]);
                acc[2 * q][1]     = ffma2(slo, wb2, acc[2 * q][1]);
                acc[2 * q + 1][0] = ffma2(shi, wa2, acc[2 * q + 1][0]);
                acc[2 * q + 1][1] = ffma2(shi, wb2, acc[2 * q + 1][1]);
            }
        }
    }

    float* ob = out + ((size_t)(b * SS) + t0 + wg * 16) * DD;
#pragma unroll
    for (int p = 0; p < 8; p++) {
        ob[(size_t)(2 * p) * DD + dtid]           = acc[p][0].x;
        ob[(size_t)(2 * p + 1) * DD + dtid]       = acc[p][0].y;
        ob[(size_t)(2 * p) * DD + 512 + dtid]     = acc[p][1].x;
        ob[(size_t)(2 * p + 1) * DD + 512 + dtid] = acc[p][1].y;
    }
}

// ---------------- launch ----------------
extern "C" void kernel_launch(void* const* d_in, const int* in_sizes, int n_in,
                              void* d_out, int out_size) {
    const float* x   = (const float*)d_in[0];
    const float* td  = (const float*)d_in[1];
    const float* tf  = (const float*)d_in[2];
    const float* kw  = (const float*)d_in[3];
    const float* vw  = (const float*)d_in[4];
    const float* ow  = (const float*)d_in[5];
    const float* tsg = (const float*)d_in[6];
    const float* lnw = (const float*)d_in[7];
    const float* lnb = (const float*)d_in[8];
    float* out = (float*)d_out;

    const int SMEM_A = 34048 * (int)sizeof(float);   // 136192 B
    cudaFuncSetAttribute(kernelA, cudaFuncAttributeMaxDynamicSharedMemorySize, SMEM_A);

    prep_a<<<(DD * 128) / 256, 256>>>(kw, vw, lnw, tsg, td, tf);
    prep_ow<<<64, 256>>>(ow);
    prep_b<<<128, 256>>>(kw, vw, lnb);
    kernelA<<<BB * (SS / TILE_A), 512, SMEM_A>>>(x);
    int write_last = (out_size >= BB * SS * DD + BB * NN) ? 1 : 0;
    scan_carry<<<1, 512>>>(td, out + (size_t)BB * SS * DD, write_last);
    kernelC<<<BB * (SS / TILE_C), 1024>>>(out);
}

// round 7
// speedup vs baseline: 1.1128x; 1.1128x over previous
#include <cuda_runtime.h>
#include <math.h>

#define BB 8
#define SS 4096
#define DD 1024
#define NN 64
#define SHIFT 2048
#define NCH 128
#define CHL 32
#define TILE_A 64
#define TILE_C 32

// ---------------- scratch (device globals) ----------------
__device__ float g_wT[DD * 128];            // [d][o]: o=2n -> lnw*kw, o=2n+1 -> lnw*vw
__device__ float g_wsum[128];
__device__ float g_lbsum[128];
__device__ float g_gate[DD];
__device__ float g_w[NN];                   // exp(time_decay)
__device__ float g_exptf[NN];               // exp(time_first)
__device__ float4 g_owQ[16 * DD];           // [n4][d] = ow[d][4n4..4n4+3]
__device__ float g_wkv[BB * SS * NN];
__device__ float g_chunk[BB * NCH * NN];
__device__ float g_carry[BB * NCH * NN];

// ---------------- packed fp32x2 FMA (sm_103a FFMA2) ----------------
__device__ __forceinline__ float2 ffma2(float2 a, float2 b, float2 c) {
    float2 d;
    asm("fma.rn.f32x2 %0, %1, %2, %3;"
        : "=l"(*reinterpret_cast<unsigned long long*>(&d))
        : "l"(*reinterpret_cast<unsigned long long*>(&a)),
          "l"(*reinterpret_cast<unsigned long long*>(&b)),
          "l"(*reinterpret_cast<unsigned long long*>(&c)));
    return d;
}

// ---------------- prep kernels ----------------
__global__ void prep_a(const float* __restrict__ kw, const float* __restrict__ vw,
                       const float* __restrict__ lnw, const float* __restrict__ tsg,
                       const float* __restrict__ td, const float* __restrict__ tf) {
    int idx = blockIdx.x * 256 + threadIdx.x;   // 0..131071
    int d = idx >> 7;
    int o = idx & 127;
    int n = o >> 1;
    const float* src = (o & 1) ? vw : kw;
    g_wT[idx] = lnw[d] * src[n * DD + d];
    if (o == 0) g_gate[d] = 1.f / (1.f + expf(-tsg[d]));
    if (idx < NN) g_w[idx] = expf(td[idx]);
    else if (idx < 2 * NN) g_exptf[idx - NN] = expf(tf[idx - NN]);
}

__global__ void prep_ow(const float* __restrict__ ow) {
    int idx = blockIdx.x * 256 + threadIdx.x;   // 0..16383
    int d = idx & (DD - 1);
    int n4 = idx >> 10;
    g_owQ[idx] = *reinterpret_cast<const float4*>(&ow[d * NN + 4 * n4]);
}

__global__ void prep_b(const float* __restrict__ kw, const float* __restrict__ vw,
                       const float* __restrict__ lnb) {
    __shared__ float red[2][8];
    int o = blockIdx.x;
    int n = o >> 1;
    const float* src = (o & 1) ? vw : kw;
    int tid = threadIdx.x;
    float ws = 0.f, lb = 0.f;
    for (int d = tid; d < DD; d += 256) {
        ws += g_wT[d * 128 + o];
        lb += lnb[d] * src[n * DD + d];
    }
#pragma unroll
    for (int off = 16; off; off >>= 1) {
        ws += __shfl_xor_sync(0xffffffffu, ws, off);
        lb += __shfl_xor_sync(0xffffffffu, lb, off);
    }
    if ((tid & 31) == 0) { red[0][tid >> 5] = ws; red[1][tid >> 5] = lb; }
    __syncthreads();
    if (tid == 0) {
        float a = 0.f, c = 0.f;
#pragma unroll
        for (int i = 0; i < 8; i++) { a += red[0][i]; c += red[1][i]; }
        g_wsum[o] = a;
        g_lbsum[o] = c;
    }
}

// ---------------- kernel A: blend + LN(folded) + KV proj + wkv + chunk sums ----------------
// grid: BB*(SS/64) = 512 blocks, 256 threads, occ 2
// smem: wsm[128*128] (64KB) | xs[64*128] (32KB) | mu[64] | inv[64]
__global__ void __launch_bounds__(256, 2)
kernelA(const float* __restrict__ x) {
    extern __shared__ float sm[];
    float* wsm = sm;                 // 16384 floats
    float* xs  = sm + 16384;         // 8192 floats
    float* mu_s = sm + 24576;        // 64
    float* inv_s = mu_s + 64;        // 64

    int b = blockIdx.x >> 6;
    int cb = blockIdx.x & 63;
    int t0 = cb * TILE_A;
    int tid = threadIdx.x;
    int lane = tid & 31;
    int warp = tid >> 5;

    float st_sum[8], st_sq[8];
#pragma unroll
    for (int e = 0; e < 8; e++) { st_sum[e] = 0.f; st_sq[e] = 0.f; }

    float2 acc[8][2];
#pragma unroll
    for (int i = 0; i < 8; i++) { acc[i][0] = make_float2(0.f, 0.f); acc[i][1] = make_float2(0.f, 0.f); }

    for (int ch = 0; ch < 8; ch++) {
        __syncthreads();
        // stage weight chunk (128 d x 128 cols = 4096 float4)
        {
            const float4* src = reinterpret_cast<const float4*>(&g_wT[ch * 16384]);
            float4* dst = reinterpret_cast<float4*>(wsm);
#pragma unroll
            for (int q = 0; q < 16; q++) dst[q * 256 + tid] = src[q * 256 + tid];
        }
        // stage xs chunk with blend + stats (64 rows x 128 d = 2048 float4)
#pragma unroll
        for (int e = 0; e < 8; e++) {
            int idx = e * 256 + tid;          // 0..2047
            int row = idx >> 5;               // = e*8 + warp
            int c4 = idx & 31;
            int t = t0 + row;
            size_t base  = ((size_t)(b * SS) + t) * DD + ch * 128 + c4 * 4;
            size_t basec = ((size_t)(b * SS) + (t ^ SHIFT)) * DD + ch * 128 + c4 * 4;
            float4 xv = *reinterpret_cast<const float4*>(x + base);
            float4 xc = *reinterpret_cast<const float4*>(x + basec);
            float4 g  = *reinterpret_cast<const float4*>(&g_gate[ch * 128 + c4 * 4]);
            float4 s;
            s.x = xv.x + g.x * (xc.x - xv.x);
            s.y = xv.y + g.y * (xc.y - xv.y);
            s.z = xv.z + g.z * (xc.z - xv.z);
            s.w = xv.w + g.w * (xc.w - xv.w);
            st_sum[e] += s.x + s.y + s.z + s.w;
            st_sq[e]  += s.x * s.x + s.y * s.y + s.z * s.z + s.w * s.w;
            *reinterpret_cast<float4*>(&xs[row * 128 + c4 * 4]) = s;
        }
        __syncthreads();

        if (ch == 7) {
            // finalize LN stats: lanes of warp w hold rows {e*8+warp}
#pragma unroll
            for (int e = 0; e < 8; e++) {
                float s = st_sum[e], q = st_sq[e];
#pragma unroll
                for (int off = 16; off; off >>= 1) {
                    s += __shfl_xor_sync(0xffffffffu, s, off);
                    q += __shfl_xor_sync(0xffffffffu, q, off);
                }
                if (lane == 0) {
                    int row = e * 8 + warp;
                    float mu = s * (1.f / DD);
                    float var = q * (1.f / DD) - mu * mu;
                    mu_s[row] = mu;
                    inv_s[row] = rsqrtf(var + 1e-5f);
                }
            }
        }

        // GEMM over this chunk: warp owns rows warp*8..+7, lane owns cols lane*4..+3
        const float* aB = &xs[(warp * 8) * 128];
#pragma unroll 8
        for (int dl4 = 0; dl4 < 32; dl4++) {
            float4 wv[4];
#pragma unroll
            for (int k = 0; k < 4; k++)
                wv[k] = *reinterpret_cast<const float4*>(&wsm[(dl4 * 4 + k) * 128 + lane * 4]);
            float4 av[8];
#pragma unroll
            for (int i = 0; i < 8; i++)
                av[i] = *reinterpret_cast<const float4*>(&aB[i * 128 + dl4 * 4]);
#pragma unroll
            for (int i = 0; i < 8; i++) {
                float2 p;
                p = make_float2(av[i].x, av[i].x);
                acc[i][0] = ffma2(p, make_float2(wv[0].x, wv[0].y), acc[i][0]);
                acc[i][1] = ffma2(p, make_float2(wv[0].z, wv[0].w), acc[i][1]);
                p = make_float2(av[i].y, av[i].y);
                acc[i][0] = ffma2(p, make_float2(wv[1].x, wv[1].y), acc[i][0]);
                acc[i][1] = ffma2(p, make_float2(wv[1].z, wv[1].w), acc[i][1]);
                p = make_float2(av[i].z, av[i].z);
                acc[i][0] = ffma2(p, make_float2(wv[2].x, wv[2].y), acc[i][0]);
                acc[i][1] = ffma2(p, make_float2(wv[2].z, wv[2].w), acc[i][1]);
                p = make_float2(av[i].w, av[i].w);
                acc[i][0] = ffma2(p, make_float2(wv[3].x, wv[3].y), acc[i][0]);
                acc[i][1] = ffma2(p, make_float2(wv[3].z, wv[3].w), acc[i][1]);
            }
        }
    }

    // ---- epilogue ----
    __syncthreads();
    float* wkv_s = wsm;                     // 64*64 floats overlay
    int n0 = lane * 2;
    int n1 = n0 + 1;
#pragma unroll
    for (int i = 0; i < 8; i++) {
        int r = warp * 8 + i;
        int t = t0 + r;
        float mu = mu_s[r], inv = inv_s[r];
        float k0 = inv * (acc[i][0].x - mu * g_wsum[2 * n0])     + g_lbsum[2 * n0];
        float v0 = inv * (acc[i][0].y - mu * g_wsum[2 * n0 + 1]) + g_lbsum[2 * n0 + 1];
        float wk0 = expf(-g_exptf[n0] * k0) * v0;
        float k1 = inv * (acc[i][1].x - mu * g_wsum[2 * n1])     + g_lbsum[2 * n1];
        float v1 = inv * (acc[i][1].y - mu * g_wsum[2 * n1 + 1]) + g_lbsum[2 * n1 + 1];
        float wk1 = expf(-g_exptf[n1] * k1) * v1;
        float2 wv = make_float2(wk0, wk1);
        *reinterpret_cast<float2*>(&g_wkv[((size_t)(b * SS) + t) * NN + n0]) = wv;
        *reinterpret_cast<float2*>(&wkv_s[r * NN + n0]) = wv;
    }
    __syncthreads();
    if (tid < 128) {
        int sub = tid >> 6;                 // 0..1
        int n = tid & 63;
        float w = g_w[n];
        float a = 0.f;
#pragma unroll
        for (int r = 0; r < 32; r++) a = a * w + wkv_s[(sub * 32 + r) * NN + n];
        g_chunk[((size_t)b * NCH + cb * 2 + sub) * NN + n] = a;
    }
}

// ---------------- carry prefix over chunks ----------------
__global__ void scan_carry(const float* __restrict__ td, float* __restrict__ lastout,
                           int write_last) {
    int tid = threadIdx.x;                  // 512 threads
    int n = tid & (NN - 1);
    int b = tid >> 6;
    float wL = expf((float)CHL * td[n]);
    float carry = 0.f;
    for (int c0 = 0; c0 < NCH; c0 += 8) {
        float v[8];
#pragma unroll
        for (int i = 0; i < 8; i++) v[i] = g_chunk[((size_t)b * NCH + c0 + i) * NN + n];
#pragma unroll
        for (int i = 0; i < 8; i++) {
            g_carry[((size_t)b * NCH + c0 + i) * NN + n] = carry;
            carry = carry * wL + v[i];
        }
    }
    if (write_last) lastout[b * NN + n] = carry;
}

// ---------------- kernel C: fused scan + output projection ----------------
// grid 1024, 1024 threads (32 warps). wg = tid>>9 owns rows [16wg,16wg+16);
// dtid = tid&511 owns d0=dtid, d1=dtid+512.
#define SPITCH 36
__global__ void __launch_bounds__(1024, 1)
kernelC(float* __restrict__ out) {
    __shared__ float wk[TILE_C * NN];       // 2048
    __shared__ float sT[NN * SPITCH];       // 2304

    int b = blockIdx.x >> 7;
    int c = blockIdx.x & 127;
    int t0 = c * TILE_C;
    int tid = threadIdx.x;
    int wg = tid >> 9;
    int dtid = tid & 511;

    if (tid < 512)
        reinterpret_cast<float4*>(wk)[tid] =
            reinterpret_cast<const float4*>(&g_wkv[((size_t)(b * SS) + t0) * NN])[tid];
    __syncthreads();

    if (tid < NN) {
        int n = tid;
        float w = g_w[n];
        float st = g_carry[((size_t)b * NCH + c) * NN + n];
#pragma unroll
        for (int r = 0; r < TILE_C; r++) {
            st = st * w + wk[r * NN + n];
            sT[n * SPITCH + r] = st;
        }
    }
    __syncthreads();

    float2 acc[8][2];
#pragma unroll
    for (int p = 0; p < 8; p++) { acc[p][0] = make_float2(0.f, 0.f); acc[p][1] = make_float2(0.f, 0.f); }

    const float* sBase = &sT[wg * 16];
#pragma unroll 2
    for (int n4 = 0; n4 < 16; n4++) {
        float4 wA = __ldg(&g_owQ[n4 * 1024 + dtid]);
        float4 wB = __ldg(&g_owQ[n4 * 1024 + 512 + dtid]);
#pragma unroll
        for (int j = 0; j < 4; j++) {
            int n = 4 * n4 + j;
            float wa = (j == 0) ? wA.x : (j == 1) ? wA.y : (j == 2) ? wA.z : wA.w;
            float wb = (j == 0) ? wB.x : (j == 1) ? wB.y : (j == 2) ? wB.z : wB.w;
            float2 wa2 = make_float2(wa, wa);
            float2 wb2 = make_float2(wb, wb);
            const float* sb = sBase + n * SPITCH;
#pragma unroll
            for (int q = 0; q < 4; q++) {
                float4 s4 = *reinterpret_cast<const float4*>(sb + 4 * q);
                float2 slo = make_float2(s4.x, s4.y);
                float2 shi = make_float2(s4.z, s4.w);
                acc[2 * q][0]     = ffma2(slo, wa2, acc[2 * q][0]);
                acc[2 * q][1]     = ffma2(slo, wb2, acc[2 * q][1]);
                acc[2 * q + 1][0] = ffma2(shi, wa2, acc[2 * q + 1][0]);
                acc[2 * q + 1][1] = ffma2(shi, wb2, acc[2 * q + 1][1]);
            }
        }
    }

    float* ob = out + ((size_t)(b * SS) + t0 + wg * 16) * DD;
#pragma unroll
    for (int p = 0; p < 8; p++) {
        ob[(size_t)(2 * p) * DD + dtid]           = acc[p][0].x;
        ob[(size_t)(2 * p + 1) * DD + dtid]       = acc[p][0].y;
        ob[(size_t)(2 * p) * DD + 512 + dtid]     = acc[p][1].x;
        ob[(size_t)(2 * p + 1) * DD + 512 + dtid] = acc[p][1].y;
    }
}

// ---------------- launch ----------------
extern "C" void kernel_launch(void* const* d_in, const int* in_sizes, int n_in,
                              void* d_out, int out_size) {
    const float* x   = (const float*)d_in[0];
    const float* td  = (const float*)d_in[1];
    const float* tf  = (const float*)d_in[2];
    const float* kw  = (const float*)d_in[3];
    const float* vw  = (const float*)d_in[4];
    const float* ow  = (const float*)d_in[5];
    const float* tsg = (const float*)d_in[6];
    const float* lnw = (const float*)d_in[7];
    const float* lnb = (const float*)d_in[8];
    float* out = (float*)d_out;

    const int SMEM_A = (16384 + 8192 + 128) * (int)sizeof(float);   // 98816 B
    cudaFuncSetAttribute(kernelA, cudaFuncAttributeMaxDynamicSharedMemorySize, SMEM_A);

    prep_a<<<(DD * 128) / 256, 256>>>(kw, vw, lnw, tsg, td, tf);
    prep_ow<<<64, 256>>>(ow);
    prep_b<<<128, 256>>>(kw, vw, lnb);
    kernelA<<<BB * (SS / TILE_A), 256, SMEM_A>>>(x);
    int write_last = (out_size >= BB * SS * DD + BB * NN) ? 1 : 0;
    scan_carry<<<1, 512>>>(td, out + (size_t)BB * SS * DD, write_last);
    kernelC<<<BB * (SS / TILE_C), 1024>>>(out);
}